// round 2
// baseline (speedup 1.0000x reference)
#include <cuda_runtime.h>
#include <cuda_bf16.h>
#include <cstdint>

// MeanAggregator: out[i,:] = mean_{e<EPN} features[edge_dst[i*EPN+e], :], D=128 f32.
// One warp per node; lane l owns float4 columns [4l,4l+4).
// R2 change: structurally force MLP=EPN — load ALL indices, then issue ALL 17
// feature LDG.128s into distinct registers, THEN reduce (pairwise tree).
// Baseline (R1) had regs=32 => ptxas serialized loads, latency-exposed at L2=63%.

#define D_DIM 128

template <int EPN>
__global__ __launch_bounds__(256) void mean_agg_kernel_fixed(
    const float* __restrict__ feat,
    const int*   __restrict__ edge_dst,
    float*       __restrict__ out,
    int B)
{
    const int warp = (blockIdx.x * blockDim.x + threadIdx.x) >> 5;
    const int lane = threadIdx.x & 31;
    if (warp >= B) return;

    const int* __restrict__ idx = edge_dst + (size_t)warp * EPN;

    // Phase 1: all indices (uniform per warp -> broadcast loads).
    int nb[EPN];
#pragma unroll
    for (int e = 0; e < EPN; ++e) nb[e] = __ldg(idx + e);

    // Phase 2: all feature gathers into distinct registers (MLP = EPN).
    float4 v[EPN];
#pragma unroll
    for (int e = 0; e < EPN; ++e) {
        v[e] = __ldg(reinterpret_cast<const float4*>(
                         feat + (size_t)nb[e] * D_DIM) + lane);
    }

    // Phase 3: pairwise-tree reduction (short FADD dependency chains).
#pragma unroll
    for (int stride = 1; stride < EPN; stride <<= 1) {
#pragma unroll
        for (int e = 0; e + stride < EPN; e += 2 * stride) {
            v[e].x += v[e + stride].x;
            v[e].y += v[e + stride].y;
            v[e].z += v[e + stride].z;
            v[e].w += v[e + stride].w;
        }
    }

    const float inv = 1.0f / (float)EPN;
    float4 r;
    r.x = v[0].x * inv; r.y = v[0].y * inv;
    r.z = v[0].z * inv; r.w = v[0].w * inv;

    reinterpret_cast<float4*>(out + (size_t)warp * D_DIM)[lane] = r;
}

// General fallback: runtime EPN, batches of 8 in-flight gathers.
__global__ __launch_bounds__(256) void mean_agg_kernel_dyn(
    const float* __restrict__ feat,
    const int*   __restrict__ edge_dst,
    float*       __restrict__ out,
    int B, int epn)
{
    const int warp = (blockIdx.x * blockDim.x + threadIdx.x) >> 5;
    const int lane = threadIdx.x & 31;
    if (warp >= B) return;

    const int* __restrict__ idx = edge_dst + (size_t)warp * epn;

    float4 acc = make_float4(0.f, 0.f, 0.f, 0.f);
    int e = 0;
    for (; e + 8 <= epn; e += 8) {
        int nb[8];
#pragma unroll
        for (int j = 0; j < 8; ++j) nb[j] = __ldg(idx + e + j);
        float4 v[8];
#pragma unroll
        for (int j = 0; j < 8; ++j)
            v[j] = __ldg(reinterpret_cast<const float4*>(
                             feat + (size_t)nb[j] * D_DIM) + lane);
#pragma unroll
        for (int j = 0; j < 8; ++j) {
            acc.x += v[j].x; acc.y += v[j].y;
            acc.z += v[j].z; acc.w += v[j].w;
        }
    }
    for (; e < epn; ++e) {
        const int nb = __ldg(idx + e);
        const float4 v = __ldg(reinterpret_cast<const float4*>(
                                   feat + (size_t)nb * D_DIM) + lane);
        acc.x += v.x; acc.y += v.y; acc.z += v.z; acc.w += v.w;
    }

    const float inv = 1.0f / (float)epn;
    acc.x *= inv; acc.y *= inv; acc.z *= inv; acc.w *= inv;
    reinterpret_cast<float4*>(out + (size_t)warp * D_DIM)[lane] = acc;
}

extern "C" void kernel_launch(void* const* d_in, const int* in_sizes, int n_in,
                              void* d_out, int out_size)
{
    const float* feat     = (const float*)d_in[0];
    const int*   edge_dst = (const int*)d_in[2];
    float*       out      = (float*)d_out;

    const int B   = out_size / D_DIM;   // 50000
    const int E   = in_sizes[2];        // 850000
    const int epn = E / B;              // 17

    const int threads = 256;            // 8 warps/block
    const int blocks  = (B * 32 + threads - 1) / threads;

    if (epn == 17) {
        mean_agg_kernel_fixed<17><<<blocks, threads>>>(feat, edge_dst, out, B);
    } else {
        mean_agg_kernel_dyn<<<blocks, threads>>>(feat, edge_dst, out, B, epn);
    }
}